// round 10
// baseline (speedup 1.0000x reference)
#include <cuda_runtime.h>
#include <cuda_fp16.h>
#include <math.h>
#include <stdint.h>

#define CCH 512
#define NPX 4096
typedef __half fp16;

static const size_t NH  = (size_t)NPX * CCH;
static const size_t NN  = (size_t)NPX * NPX;
static const size_t NQK = (size_t)NPX * 1024;
#define WS ((size_t)CCH * CCH)

// ---------------- static scratch ----------------
__device__ fp16  g_ht[(size_t)2 * NPX * CCH];    // GN output [B][N][C]
__device__ fp16  g_w[(size_t)4 * CCH * CCH];     // wq,wk,wv,wp fp16
__device__ fp16  g_wvT[(size_t)CCH * CCH];       // wv^T fp16
__device__ fp16  g_wpv[(size_t)CCH * CCH];       // Wpv = wp@wv fp16
__device__ float g_bpv[CCH];                     // wp@bv
__device__ float g_bqk[1024];                    // concat bq|bk
__device__ fp16  g_qk[(size_t)2 * NPX * 1024];   // [B][N][1024]: Q|K
__device__ fp16  g_wv16[(size_t)2 * CCH * NPX];  // WpV [B][C][N]
__device__ fp16  g_E[(size_t)2 * NPX * NPX];     // exp(scores) fp16
__device__ float g_part[(size_t)2 * NPX * 16];   // per-(row, nblock) partial sums
__device__ float g_invs[(size_t)2 * NPX];        // 1/rowsum

// ---------------- helpers ----------------
__device__ __forceinline__ uint32_t smem_u32(const void* p) {
    uint32_t a;
    asm("{ .reg .u64 t; cvta.to.shared.u64 t, %1; cvt.u32.u64 %0, t; }" : "=r"(a) : "l"(p));
    return a;
}
__device__ __forceinline__ uint32_t pack2(fp16 a, fp16 b) {
    __half2 t; t.x = a; t.y = b;
    return *reinterpret_cast<uint32_t*>(&t);
}
__device__ __forceinline__ void cp16(uint32_t s, const void* g) {
    asm volatile("cp.async.cg.shared.global [%0], [%1], 16;" :: "r"(s), "l"(g));
}
__device__ __forceinline__ void ldsm4(uint32_t* r, uint32_t addr) {
    asm volatile("ldmatrix.sync.aligned.m8n8.x4.shared.b16 {%0,%1,%2,%3}, [%4];"
        : "=r"(r[0]), "=r"(r[1]), "=r"(r[2]), "=r"(r[3]) : "r"(addr));
}
__device__ __forceinline__ void mma16816(float* d, const uint32_t* a, uint32_t b0, uint32_t b1) {
    asm volatile("mma.sync.aligned.m16n8k16.row.col.f32.f16.f16.f32 "
        "{%0,%1,%2,%3}, {%4,%5,%6,%7}, {%8,%9}, {%0,%1,%2,%3};"
        : "+f"(d[0]), "+f"(d[1]), "+f"(d[2]), "+f"(d[3])
        : "r"(a[0]), "r"(a[1]), "r"(a[2]), "r"(a[3]), "r"(b0), "r"(b1));
}

// ---------------- weight convert ----------------
__global__ void __launch_bounds__(256) wconv_kernel(const float* __restrict__ w0,
                                                    const float* __restrict__ w1,
                                                    const float* __restrict__ w2,
                                                    const float* __restrict__ w3,
                                                    fp16* __restrict__ o) {
    size_t i = (size_t)blockIdx.x * 256 + threadIdx.x;
    size_t which = i / WS, r = i - which * WS;
    const float* w = (which == 0) ? w0 : (which == 1) ? w1 : (which == 2) ? w2 : w3;
    o[i] = __float2half(w[r]);
}

// ---------------- wv transpose (fp16) ----------------
__global__ void __launch_bounds__(256) wtrans_kernel(const fp16* __restrict__ src,
                                                     fp16* __restrict__ dst) {
    __shared__ fp16 t[32][33];
    int bx = blockIdx.x * 32, by = blockIdx.y * 32;
    int tx = threadIdx.x & 31, ty = threadIdx.x >> 5;   // 32 x 8
    #pragma unroll
    for (int r = 0; r < 32; r += 8)
        t[ty + r][tx] = src[(size_t)(by + ty + r) * CCH + bx + tx];
    __syncthreads();
    #pragma unroll
    for (int r = 0; r < 32; r += 8)
        dst[(size_t)(bx + ty + r) * CCH + by + tx] = t[tx][ty + r];
}

// ---------------- bias prep: bqk concat + bpv = wp@bv ----------------
__global__ void prep_kernel(const float* __restrict__ bq, const float* __restrict__ bk) {
    int i = blockIdx.x * 512 + threadIdx.x;
    g_bqk[i] = (i < 512) ? bq[i] : bk[i - 512];
}
__global__ void __launch_bounds__(256) bpv_kernel(const float* __restrict__ wp,
                                                  const float* __restrict__ bv) {
    int c = blockIdx.x * 256 + threadIdx.x;
    const float* row = wp + (size_t)c * CCH;
    float s = 0.f;
    for (int j = 0; j < CCH; j += 4) {
        float4 a = *(const float4*)(row + j);
        float4 b = *(const float4*)(bv + j);
        s += a.x * b.x + a.y * b.y + a.z * b.z + a.w * b.w;
    }
    g_bpv[c] = s;
}

// ---------------- GroupNorm + transpose -> fp16 [B][N][C] ----------------
__global__ void __launch_bounds__(256) gn_kernel(const float* __restrict__ x,
                                                 const float* __restrict__ gamma,
                                                 const float* __restrict__ beta) {
    int b = blockIdx.x >> 5;
    int g = blockIdx.x & 31;
    const size_t base = ((size_t)b * CCH + (size_t)g * 16) * NPX;
    const float4* xp = (const float4*)(x + base);
    const int TOT4 = 16 * NPX / 4;
    int tid = threadIdx.x;

    float s = 0.f, ss = 0.f;
    for (int i = tid; i < TOT4; i += 256) {
        float4 v = xp[i];
        s  += v.x + v.y + v.z + v.w;
        ss += v.x * v.x + v.y * v.y + v.z * v.z + v.w * v.w;
    }
    __shared__ float rs[8], rss[8];
    #pragma unroll
    for (int o = 16; o > 0; o >>= 1) {
        s  += __shfl_xor_sync(0xffffffffu, s, o);
        ss += __shfl_xor_sync(0xffffffffu, ss, o);
    }
    if ((tid & 31) == 0) { rs[tid >> 5] = s; rss[tid >> 5] = ss; }
    __syncthreads();
    float S = 0.f, SS = 0.f;
    #pragma unroll
    for (int w = 0; w < 8; w++) { S += rs[w]; SS += rss[w]; }
    const float inv_cnt = 1.0f / (float)(16 * NPX);
    float mean = S * inv_cnt;
    float var  = SS * inv_cnt - mean * mean;
    float rstd = rsqrtf(var + 1e-6f);

    __shared__ float sga[16], sbe[16];
    if (tid < 16) {
        int c = g * 16 + tid;
        float ga = gamma[c] * rstd;
        sga[tid] = ga;
        sbe[tid] = beta[c] - mean * ga;
    }
    __shared__ float xs[16][256];
    __syncthreads();

    for (int p0 = 0; p0 < NPX; p0 += 256) {
        #pragma unroll
        for (int c = 0; c < 16; c++) xs[c][tid] = x[base + (size_t)c * NPX + p0 + tid];
        __syncthreads();
        uint32_t hw[8];
        #pragma unroll
        for (int c2 = 0; c2 < 8; c2++) {
            float v0 = xs[2 * c2][tid]     * sga[2 * c2]     + sbe[2 * c2];
            float v1 = xs[2 * c2 + 1][tid] * sga[2 * c2 + 1] + sbe[2 * c2 + 1];
            hw[c2] = pack2(__float2half(v0), __float2half(v1));
        }
        size_t o = ((size_t)b * NPX + p0 + tid) * CCH + g * 16;
        ((uint4*)(g_ht + o))[0] = make_uint4(hw[0], hw[1], hw[2], hw[3]);
        ((uint4*)(g_ht + o))[1] = make_uint4(hw[4], hw[5], hw[6], hw[7]);
        __syncthreads();
    }
}

// ---------------- rowsum reduce: inv = 1/sum(partials) ----------------
__global__ void rowsum_kernel() {
    int i = blockIdx.x * 256 + threadIdx.x;      // 0..8191
    const float* p = g_part + (size_t)i * 16;
    float s = 0.f;
    #pragma unroll
    for (int k = 0; k < 16; k++) s += p[k];
    g_invs[i] = 1.0f / s;
}

// ================= f32-acc GEMM: CTA 128x256, warp 64x64, BK=64, 3-stage =================
#define ROWB  144
#define STG_A (128 * ROWB)
#define STG_B (256 * ROWB)
#define STG   (STG_A + STG_B)

#define GEMM_MAINLOOP() \
    uint32_t base = smem_u32(smemraw); \
    int wm = wid & 1, wn = wid >> 1; \
    const int nch = K >> 6; \
    float acc[4][8][4]; \
    _Pragma("unroll") \
    for (int a_ = 0; a_ < 4; a_++) \
        _Pragma("unroll") \
        for (int b_ = 0; b_ < 8; b_++) \
            _Pragma("unroll") \
            for (int c_ = 0; c_ < 4; c_++) acc[a_][b_][c_] = 0.f; \
    auto load_chunk = [&](int i) { \
        int st = i % 3; \
        size_t kb = (size_t)i * 64; \
        uint32_t sa = base + st * STG; \
        uint32_t sb = sa + STG_A; \
        _Pragma("unroll") \
        for (int r = 0; r < 4; r++) { \
            int u = tid + r * 256; \
            int row = u >> 3, cs = u & 7; \
            cp16(sa + (uint32_t)(row * ROWB + cs * 16), \
                 A + (size_t)(m0 + row) * ldA + kb + cs * 8); \
        } \
        _Pragma("unroll") \
        for (int r = 0; r < 8; r++) { \
            int u = tid + r * 256; \
            int row = u >> 3, cs = u & 7; \
            cp16(sb + (uint32_t)(row * ROWB + cs * 16), \
                 B + (size_t)(n0 + row) * ldB + kb + cs * 8); \
        } \
    }; \
    load_chunk(0); \
    asm volatile("cp.async.commit_group;" ::: "memory"); \
    if (nch > 1) load_chunk(1); \
    asm volatile("cp.async.commit_group;" ::: "memory"); \
    uint32_t a_off[4], b_off[4]; \
    _Pragma("unroll") \
    for (int mi = 0; mi < 4; mi++) { \
        int row = wm * 64 + mi * 16 + (lane & 15); \
        a_off[mi] = (uint32_t)(row * ROWB + ((lane >> 4) * 8) * 2); \
    } \
    _Pragma("unroll") \
    for (int nb = 0; nb < 4; nb++) { \
        int row = wn * 64 + nb * 16 + ((lane >> 4) << 3) + (lane & 7); \
        b_off[nb] = (uint32_t)(row * ROWB + ((((lane >> 3) & 1) << 3)) * 2); \
    } \
    for (int i = 0; i < nch; i++) { \
        if (i < nch - 1) asm volatile("cp.async.wait_group 1;" ::: "memory"); \
        else             asm volatile("cp.async.wait_group 0;" ::: "memory"); \
        __syncthreads(); \
        if (i + 2 < nch) { \
            load_chunk(i + 2); \
            asm volatile("cp.async.commit_group;" ::: "memory"); \
        } \
        uint32_t sa = base + (i % 3) * STG; \
        uint32_t sb = sa + STG_A; \
        uint32_t afr[2][4][4], bfr[2][4][4]; \
        _Pragma("unroll") \
        for (int mi = 0; mi < 4; mi++) ldsm4(afr[0][mi], sa + a_off[mi]); \
        _Pragma("unroll") \
        for (int nb = 0; nb < 4; nb++) ldsm4(bfr[0][nb], sb + b_off[nb]); \
        _Pragma("unroll") \
        for (int kk = 0; kk < 4; kk++) { \
            int cur = kk & 1, nxt = cur ^ 1; \
            if (kk < 3) { \
                uint32_t ko = (uint32_t)((kk + 1) * 32); \
                _Pragma("unroll") \
                for (int mi = 0; mi < 4; mi++) ldsm4(afr[nxt][mi], sa + a_off[mi] + ko); \
                _Pragma("unroll") \
                for (int nb = 0; nb < 4; nb++) ldsm4(bfr[nxt][nb], sb + b_off[nb] + ko); \
            } \
            _Pragma("unroll") \
            for (int mi = 0; mi < 4; mi++) \
                _Pragma("unroll") \
                for (int ni = 0; ni < 8; ni++) \
                    mma16816(acc[mi][ni], afr[cur][mi], \
                             bfr[cur][ni >> 1][(ni & 1) * 2], bfr[cur][ni >> 1][(ni & 1) * 2 + 1]); \
        } \
    }

// ---- general GEMM ----
__global__ void gemm_hmma(
    const fp16* __restrict__ A, int ldA, size_t strideA,
    const fp16* __restrict__ B, int ldB, size_t strideB,
    int K,
    float* __restrict__ outF32, fp16* __restrict__ outH,
    int ldD, size_t strideD,
    float scale,
    const float* __restrict__ biasRow,
    const float* __restrict__ biasCol,
    const float* __restrict__ perN,
    const float* __restrict__ resid)
{
    extern __shared__ char smemraw[];
    int tid = threadIdx.x, wid = tid >> 5, lane = tid & 31;
    int m0 = blockIdx.y * 128, n0 = blockIdx.x * 256, bz = blockIdx.z;
    A += (size_t)bz * strideA;
    B += (size_t)bz * strideB;

    GEMM_MAINLOOP()

    int r4 = lane >> 2;
    int c2 = lane & 3;
    float* of = outF32 ? outF32 + (size_t)bz * strideD : nullptr;
    fp16* oh  = outH   ? outH   + (size_t)bz * strideD : nullptr;
    const float* rp = resid ? resid + (size_t)bz * strideD : nullptr;
    const float* pn = perN ? perN + (size_t)bz * NPX : nullptr;

    #pragma unroll
    for (int mi = 0; mi < 4; mi++) {
        #pragma unroll
        for (int half = 0; half < 2; half++) {
            int m = m0 + wm * 64 + mi * 16 + half * 8 + r4;
            float brow = biasRow ? biasRow[m] : 0.f;
            #pragma unroll
            for (int ni = 0; ni < 8; ni++) {
                int n = n0 + wn * 64 + ni * 8 + c2 * 2;
                float v0 = acc[mi][ni][half * 2 + 0] * scale;
                float v1 = acc[mi][ni][half * 2 + 1] * scale;
                if (pn) { v0 *= pn[n]; v1 *= pn[n + 1]; }
                v0 += brow; v1 += brow;
                if (biasCol) { v0 += biasCol[n]; v1 += biasCol[n + 1]; }
                size_t off = (size_t)m * ldD + n;
                if (rp) {
                    float2 q = *(const float2*)(rp + off);
                    v0 += q.x; v1 += q.y;
                }
                if (of) *(float2*)(of + off) = make_float2(v0, v1);
                if (oh) *(uint32_t*)(oh + off) = pack2(__float2half(v0), __float2half(v1));
            }
        }
    }
}

// ---- scores GEMM: writes E=exp(scale*s) fp16 + per-row partial sums ----
__global__ void gemm_scores(
    const fp16* __restrict__ A, int ldA, size_t strideA,
    const fp16* __restrict__ B, int ldB, size_t strideB,
    int K,
    fp16* __restrict__ outE, int ldD, size_t strideD,
    float scale)
{
    extern __shared__ char smemraw[];
    int tid = threadIdx.x, wid = tid >> 5, lane = tid & 31;
    int m0 = blockIdx.y * 128, n0 = blockIdx.x * 256, bz = blockIdx.z;
    A += (size_t)bz * strideA;
    B += (size_t)bz * strideB;

    GEMM_MAINLOOP()

    int r4 = lane >> 2;
    int c2 = lane & 3;
    fp16* oh = outE + (size_t)bz * strideD;
    float rsum[8];
    #pragma unroll
    for (int r = 0; r < 8; r++) rsum[r] = 0.f;

    #pragma unroll
    for (int mi = 0; mi < 4; mi++) {
        #pragma unroll
        for (int half = 0; half < 2; half++) {
            int m = m0 + wm * 64 + mi * 16 + half * 8 + r4;
            float rs = 0.f;
            #pragma unroll
            for (int ni = 0; ni < 8; ni++) {
                int n = n0 + wn * 64 + ni * 8 + c2 * 2;
                float e0 = __expf(acc[mi][ni][half * 2 + 0] * scale);
                float e1 = __expf(acc[mi][ni][half * 2 + 1] * scale);
                *(uint32_t*)(oh + (size_t)m * ldD + n) = pack2(__float2half(e0), __float2half(e1));
                rs += e0 + e1;
            }
            rsum[mi * 2 + half] = rs;
        }
    }
    #pragma unroll
    for (int r = 0; r < 8; r++) {
        rsum[r] += __shfl_xor_sync(0xffffffffu, rsum[r], 1);
        rsum[r] += __shfl_xor_sync(0xffffffffu, rsum[r], 2);
    }
    __syncthreads();
    float* sp = (float*)smemraw;
    if (c2 == 0) {
        #pragma unroll
        for (int mi = 0; mi < 4; mi++)
            #pragma unroll
            for (int half = 0; half < 2; half++) {
                int rl = wm * 64 + mi * 16 + half * 8 + r4;
                sp[rl * 4 + wn] = rsum[mi * 2 + half];
            }
    }
    __syncthreads();
    if (tid < 128) {
        float s = sp[tid * 4] + sp[tid * 4 + 1] + sp[tid * 4 + 2] + sp[tid * 4 + 3];
        g_part[((size_t)bz * NPX + m0 + tid) * 16 + blockIdx.x] = s;
    }
}

// ---------------- launch ----------------
extern "C" void kernel_launch(void* const* d_in, const int* in_sizes, int n_in,
                              void* d_out, int out_size) {
    const float* x     = (const float*)d_in[0];
    const float* gamma = (const float*)d_in[1];
    const float* beta  = (const float*)d_in[2];
    const float* wq    = (const float*)d_in[3];
    const float* bq    = (const float*)d_in[4];
    const float* wk    = (const float*)d_in[5];
    const float* bk    = (const float*)d_in[6];
    const float* wv    = (const float*)d_in[7];
    const float* bv    = (const float*)d_in[8];
    const float* wp    = (const float*)d_in[9];
    const float* bp    = (const float*)d_in[10];
    float* out = (float*)d_out;

    fp16 *ht, *w, *wvT, *wpv, *qk, *wv16, *E;
    float *bqk, *bpv, *invs;
    cudaGetSymbolAddress((void**)&ht, g_ht);
    cudaGetSymbolAddress((void**)&w, g_w);
    cudaGetSymbolAddress((void**)&wvT, g_wvT);
    cudaGetSymbolAddress((void**)&wpv, g_wpv);
    cudaGetSymbolAddress((void**)&qk, g_qk);
    cudaGetSymbolAddress((void**)&wv16, g_wv16);
    cudaGetSymbolAddress((void**)&E, g_E);
    cudaGetSymbolAddress((void**)&bqk, g_bqk);
    cudaGetSymbolAddress((void**)&bpv, g_bpv);
    cudaGetSymbolAddress((void**)&invs, g_invs);

    const int SMEM_DYN = 3 * STG;    // 162 KB
    cudaFuncSetAttribute(gemm_hmma, cudaFuncAttributeMaxDynamicSharedMemorySize, SMEM_DYN);
    cudaFuncSetAttribute(gemm_scores, cudaFuncAttributeMaxDynamicSharedMemorySize, SMEM_DYN);

    // prep (all tiny)
    wconv_kernel<<<4 * (int)(WS / 256), 256>>>(wq, wk, wv, wp, w);
    wtrans_kernel<<<dim3(16, 16), 256>>>(w + 2 * WS, wvT);
    prep_kernel<<<2, 512>>>(bq, bk);
    bpv_kernel<<<2, 256>>>(wp, bv);
    gn_kernel<<<64, 256>>>(x, gamma, beta);

    // Wpv = wp @ wv : [512,512] fp16 (tiny GEMM)
    gemm_hmma<<<dim3(2, 4, 1), 256, SMEM_DYN>>>(
        w + 3 * WS, CCH, 0, wvT, CCH, 0, CCH,
        nullptr, wpv, CCH, 0, 1.0f, nullptr, nullptr, nullptr, nullptr);

    // QK: D[4096,1024] = ht @ [wq;wk]^T + bqk -> fp16
    gemm_hmma<<<dim3(1024 / 256, NPX / 128, 2), 256, SMEM_DYN>>>(
        ht, CCH, NH, w, CCH, 0, CCH,
        nullptr, qk, 1024, NQK, 1.0f, nullptr, bqk, nullptr, nullptr);

    // WpV = Wpv @ ht^T + bpv : [512,4096] fp16
    gemm_hmma<<<dim3(NPX / 256, CCH / 128, 2), 256, SMEM_DYN>>>(
        wpv, CCH, 0, ht, CCH, NH, CCH,
        nullptr, wv16, NPX, NH, 1.0f, bpv, nullptr, nullptr, nullptr);

    // scores -> E = exp(scale * Q@K^T) fp16 + partial sums
    const float scale = 1.0f / sqrtf((float)CCH);
    gemm_scores<<<dim3(NPX / 256, NPX / 128, 2), 256, SMEM_DYN>>>(
        qk, 1024, NQK, qk + 512, 1024, NQK, CCH,
        E, NPX, NN, scale);

    rowsum_kernel<<<2 * NPX / 256, 256>>>();

    // final: out[c,i] = (sum_j WpV[c,j]*E[i,j]) * invs[i] + bp[c] + x[c,i]
    gemm_hmma<<<dim3(NPX / 256, CCH / 128, 2), 256, SMEM_DYN>>>(
        wv16, NPX, NH, E, NPX, NN, NPX,
        out, nullptr, NPX, (size_t)CCH * NPX, 1.0f, bp, nullptr, invs, x);
}

// round 11
// speedup vs baseline: 1.0656x; 1.0656x over previous
#include <cuda_runtime.h>
#include <cuda_fp16.h>
#include <math.h>
#include <stdint.h>

#define CCH 512
#define NPX 4096
typedef __half fp16;

static const size_t NH  = (size_t)NPX * CCH;
static const size_t NN  = (size_t)NPX * NPX;
static const size_t NQK = (size_t)NPX * 1024;
#define WS ((size_t)CCH * CCH)

// ---------------- static scratch ----------------
__device__ fp16  g_ht[(size_t)2 * NPX * CCH];    // GN output [B][N][C]
__device__ fp16  g_w[(size_t)4 * CCH * CCH];     // wq,wk,wv,wp fp16
__device__ fp16  g_wvT[(size_t)CCH * CCH];       // wv^T fp16
__device__ fp16  g_wpv[(size_t)CCH * CCH];       // Wpv = wp@wv fp16
__device__ float g_bpv[CCH];                     // wp@bv
__device__ float g_bqk[1024];                    // concat bq|bk
__device__ fp16  g_qk[(size_t)2 * NPX * 1024];   // [B][N][1024]: Q|K
__device__ fp16  g_wv16[(size_t)2 * CCH * NPX];  // WpV [B][C][N]
__device__ fp16  g_E[(size_t)2 * NPX * NPX];     // exp(scores) fp16
__device__ float g_part[(size_t)2 * NPX * 16];   // per-(row, nblock) partial sums

// ---------------- helpers ----------------
__device__ __forceinline__ uint32_t smem_u32(const void* p) {
    uint32_t a;
    asm("{ .reg .u64 t; cvta.to.shared.u64 t, %1; cvt.u32.u64 %0, t; }" : "=r"(a) : "l"(p));
    return a;
}
__device__ __forceinline__ uint32_t pack2(fp16 a, fp16 b) {
    __half2 t; t.x = a; t.y = b;
    return *reinterpret_cast<uint32_t*>(&t);
}
__device__ __forceinline__ void cp16(uint32_t s, const void* g) {
    asm volatile("cp.async.cg.shared.global [%0], [%1], 16;" :: "r"(s), "l"(g));
}
__device__ __forceinline__ void ldsm4(uint32_t* r, uint32_t addr) {
    asm volatile("ldmatrix.sync.aligned.m8n8.x4.shared.b16 {%0,%1,%2,%3}, [%4];"
        : "=r"(r[0]), "=r"(r[1]), "=r"(r[2]), "=r"(r[3]) : "r"(addr));
}
__device__ __forceinline__ void mma16816(float* d, const uint32_t* a, uint32_t b0, uint32_t b1) {
    asm volatile("mma.sync.aligned.m16n8k16.row.col.f32.f16.f16.f32 "
        "{%0,%1,%2,%3}, {%4,%5,%6,%7}, {%8,%9}, {%0,%1,%2,%3};"
        : "+f"(d[0]), "+f"(d[1]), "+f"(d[2]), "+f"(d[3])
        : "r"(a[0]), "r"(a[1]), "r"(a[2]), "r"(a[3]), "r"(b0), "r"(b1));
}

// ---------------- fused prep: wconv + wvT + bqk + bpv ----------------
// blocks [0,4096): elementwise fp16 convert of wq|wk|wv|wp
// blocks [4096,4352): 32x32 transpose tiles of wv (fp32 -> fp16 wvT)
// blocks [4352,4356): bqk concat
// blocks [4356,4420): bpv = wp@bv, warp per channel
__global__ void __launch_bounds__(256) prep_all(const float* __restrict__ wq,
                                                const float* __restrict__ wk,
                                                const float* __restrict__ wv,
                                                const float* __restrict__ wp,
                                                const float* __restrict__ bq,
                                                const float* __restrict__ bk,
                                                const float* __restrict__ bv) {
    int bid = blockIdx.x;
    int tid = threadIdx.x;
    if (bid < 4096) {
        size_t i = (size_t)bid * 256 + tid;
        size_t which = i / WS, r = i - which * WS;
        const float* w = (which == 0) ? wq : (which == 1) ? wk : (which == 2) ? wv : wp;
        g_w[i] = __float2half(w[r]);
    } else if (bid < 4352) {
        int t = bid - 4096;
        int bx = (t & 15) * 32, by = (t >> 4) * 32;
        int tx = tid & 31, ty = tid >> 5;    // 32 x 8
        __shared__ fp16 sm[32][33];
        #pragma unroll
        for (int r = 0; r < 32; r += 8)
            sm[ty + r][tx] = __float2half(wv[(size_t)(by + ty + r) * CCH + bx + tx]);
        __syncthreads();
        #pragma unroll
        for (int r = 0; r < 32; r += 8)
            g_wvT[(size_t)(bx + ty + r) * CCH + by + tx] = sm[tx][ty + r];
    } else if (bid < 4356) {
        int i = (bid - 4352) * 256 + tid;
        g_bqk[i] = (i < 512) ? bq[i] : bk[i - 512];
    } else {
        int wid = tid >> 5, lane = tid & 31;
        int c = (bid - 4356) * 8 + wid;
        const float* row = wp + (size_t)c * CCH;
        float s = 0.f;
        #pragma unroll
        for (int j = 0; j < 16; j++) s += row[lane + j * 32] * bv[lane + j * 32];
        #pragma unroll
        for (int o = 16; o > 0; o >>= 1) s += __shfl_xor_sync(0xffffffffu, s, o);
        if (lane == 0) g_bpv[c] = s;
    }
}

// ---------------- GroupNorm + transpose -> fp16 [B][N][C] ----------------
__global__ void __launch_bounds__(256) gn_kernel(const float* __restrict__ x,
                                                 const float* __restrict__ gamma,
                                                 const float* __restrict__ beta) {
    int b = blockIdx.x >> 5;
    int g = blockIdx.x & 31;
    const size_t base = ((size_t)b * CCH + (size_t)g * 16) * NPX;
    const float4* xp = (const float4*)(x + base);
    const int TOT4 = 16 * NPX / 4;
    int tid = threadIdx.x;

    float s = 0.f, ss = 0.f;
    for (int i = tid; i < TOT4; i += 256) {
        float4 v = xp[i];
        s  += v.x + v.y + v.z + v.w;
        ss += v.x * v.x + v.y * v.y + v.z * v.z + v.w * v.w;
    }
    __shared__ float rs[8], rss[8];
    #pragma unroll
    for (int o = 16; o > 0; o >>= 1) {
        s  += __shfl_xor_sync(0xffffffffu, s, o);
        ss += __shfl_xor_sync(0xffffffffu, ss, o);
    }
    if ((tid & 31) == 0) { rs[tid >> 5] = s; rss[tid >> 5] = ss; }
    __syncthreads();
    float S = 0.f, SS = 0.f;
    #pragma unroll
    for (int w = 0; w < 8; w++) { S += rs[w]; SS += rss[w]; }
    const float inv_cnt = 1.0f / (float)(16 * NPX);
    float mean = S * inv_cnt;
    float var  = SS * inv_cnt - mean * mean;
    float rstd = rsqrtf(var + 1e-6f);

    __shared__ float sga[16], sbe[16];
    if (tid < 16) {
        int c = g * 16 + tid;
        float ga = gamma[c] * rstd;
        sga[tid] = ga;
        sbe[tid] = beta[c] - mean * ga;
    }
    __shared__ float xs[16][256];
    __syncthreads();

    for (int p0 = 0; p0 < NPX; p0 += 256) {
        #pragma unroll
        for (int c = 0; c < 16; c++) xs[c][tid] = x[base + (size_t)c * NPX + p0 + tid];
        __syncthreads();
        uint32_t hw[8];
        #pragma unroll
        for (int c2 = 0; c2 < 8; c2++) {
            float v0 = xs[2 * c2][tid]     * sga[2 * c2]     + sbe[2 * c2];
            float v1 = xs[2 * c2 + 1][tid] * sga[2 * c2 + 1] + sbe[2 * c2 + 1];
            hw[c2] = pack2(__float2half(v0), __float2half(v1));
        }
        size_t o = ((size_t)b * NPX + p0 + tid) * CCH + g * 16;
        ((uint4*)(g_ht + o))[0] = make_uint4(hw[0], hw[1], hw[2], hw[3]);
        ((uint4*)(g_ht + o))[1] = make_uint4(hw[4], hw[5], hw[6], hw[7]);
        __syncthreads();
    }
}

// ================= f32-acc GEMM: CTA 128x256, warp 64x64, BK=64, 3-stage =================
#define ROWB  144
#define STG_A (128 * ROWB)
#define STG_B (256 * ROWB)
#define STG   (STG_A + STG_B)

#define GEMM_MAINLOOP() \
    uint32_t base = smem_u32(smemraw); \
    int wm = wid & 1, wn = wid >> 1; \
    const int nch = K >> 6; \
    float acc[4][8][4]; \
    _Pragma("unroll") \
    for (int a_ = 0; a_ < 4; a_++) \
        _Pragma("unroll") \
        for (int b_ = 0; b_ < 8; b_++) \
            _Pragma("unroll") \
            for (int c_ = 0; c_ < 4; c_++) acc[a_][b_][c_] = 0.f; \
    auto load_chunk = [&](int i) { \
        int st = i % 3; \
        size_t kb = (size_t)i * 64; \
        uint32_t sa = base + st * STG; \
        uint32_t sb = sa + STG_A; \
        _Pragma("unroll") \
        for (int r = 0; r < 4; r++) { \
            int u = tid + r * 256; \
            int row = u >> 3, cs = u & 7; \
            cp16(sa + (uint32_t)(row * ROWB + cs * 16), \
                 A + (size_t)(m0 + row) * ldA + kb + cs * 8); \
        } \
        _Pragma("unroll") \
        for (int r = 0; r < 8; r++) { \
            int u = tid + r * 256; \
            int row = u >> 3, cs = u & 7; \
            cp16(sb + (uint32_t)(row * ROWB + cs * 16), \
                 B + (size_t)(n0 + row) * ldB + kb + cs * 8); \
        } \
    }; \
    load_chunk(0); \
    asm volatile("cp.async.commit_group;" ::: "memory"); \
    if (nch > 1) load_chunk(1); \
    asm volatile("cp.async.commit_group;" ::: "memory"); \
    uint32_t a_off[4], b_off[4]; \
    _Pragma("unroll") \
    for (int mi = 0; mi < 4; mi++) { \
        int row = wm * 64 + mi * 16 + (lane & 15); \
        a_off[mi] = (uint32_t)(row * ROWB + ((lane >> 4) * 8) * 2); \
    } \
    _Pragma("unroll") \
    for (int nb = 0; nb < 4; nb++) { \
        int row = wn * 64 + nb * 16 + ((lane >> 4) << 3) + (lane & 7); \
        b_off[nb] = (uint32_t)(row * ROWB + ((((lane >> 3) & 1) << 3)) * 2); \
    } \
    for (int i = 0; i < nch; i++) { \
        if (i < nch - 1) asm volatile("cp.async.wait_group 1;" ::: "memory"); \
        else             asm volatile("cp.async.wait_group 0;" ::: "memory"); \
        __syncthreads(); \
        if (i + 2 < nch) { \
            load_chunk(i + 2); \
            asm volatile("cp.async.commit_group;" ::: "memory"); \
        } \
        uint32_t sa = base + (i % 3) * STG; \
        uint32_t sb = sa + STG_A; \
        uint32_t afr[2][4][4], bfr[2][4][4]; \
        _Pragma("unroll") \
        for (int mi = 0; mi < 4; mi++) ldsm4(afr[0][mi], sa + a_off[mi]); \
        _Pragma("unroll") \
        for (int nb = 0; nb < 4; nb++) ldsm4(bfr[0][nb], sb + b_off[nb]); \
        _Pragma("unroll") \
        for (int kk = 0; kk < 4; kk++) { \
            int cur = kk & 1, nxt = cur ^ 1; \
            if (kk < 3) { \
                uint32_t ko = (uint32_t)((kk + 1) * 32); \
                _Pragma("unroll") \
                for (int mi = 0; mi < 4; mi++) ldsm4(afr[nxt][mi], sa + a_off[mi] + ko); \
                _Pragma("unroll") \
                for (int nb = 0; nb < 4; nb++) ldsm4(bfr[nxt][nb], sb + b_off[nb] + ko); \
            } \
            _Pragma("unroll") \
            for (int mi = 0; mi < 4; mi++) \
                _Pragma("unroll") \
                for (int ni = 0; ni < 8; ni++) \
                    mma16816(acc[mi][ni], afr[cur][mi], \
                             bfr[cur][ni >> 1][(ni & 1) * 2], bfr[cur][ni >> 1][(ni & 1) * 2 + 1]); \
        } \
    }

// ---- general GEMM (fp16/fp32 out, biasRow/biasCol) ----
__global__ void gemm_hmma(
    const fp16* __restrict__ A, int ldA, size_t strideA,
    const fp16* __restrict__ B, int ldB, size_t strideB,
    int K,
    fp16* __restrict__ outH,
    int ldD, size_t strideD,
    const float* __restrict__ biasRow,
    const float* __restrict__ biasCol)
{
    extern __shared__ char smemraw[];
    int tid = threadIdx.x, wid = tid >> 5, lane = tid & 31;
    int m0 = blockIdx.y * 128, n0 = blockIdx.x * 256, bz = blockIdx.z;
    A += (size_t)bz * strideA;
    B += (size_t)bz * strideB;

    GEMM_MAINLOOP()

    int r4 = lane >> 2;
    int c2 = lane & 3;
    fp16* oh = outH + (size_t)bz * strideD;

    #pragma unroll
    for (int mi = 0; mi < 4; mi++) {
        #pragma unroll
        for (int half = 0; half < 2; half++) {
            int m = m0 + wm * 64 + mi * 16 + half * 8 + r4;
            float brow = biasRow ? biasRow[m] : 0.f;
            #pragma unroll
            for (int ni = 0; ni < 8; ni++) {
                int n = n0 + wn * 64 + ni * 8 + c2 * 2;
                float v0 = acc[mi][ni][half * 2 + 0] + brow;
                float v1 = acc[mi][ni][half * 2 + 1] + brow;
                if (biasCol) { v0 += biasCol[n]; v1 += biasCol[n + 1]; }
                *(uint32_t*)(oh + (size_t)m * ldD + n) = pack2(__float2half(v0), __float2half(v1));
            }
        }
    }
}

// ---- scores GEMM: E=exp(scale*s) fp16 + per-row partial sums ----
__global__ void gemm_scores(
    const fp16* __restrict__ A, int ldA, size_t strideA,
    const fp16* __restrict__ B, int ldB, size_t strideB,
    int K,
    fp16* __restrict__ outE, int ldD, size_t strideD,
    float scale)
{
    extern __shared__ char smemraw[];
    int tid = threadIdx.x, wid = tid >> 5, lane = tid & 31;
    int m0 = blockIdx.y * 128, n0 = blockIdx.x * 256, bz = blockIdx.z;
    A += (size_t)bz * strideA;
    B += (size_t)bz * strideB;

    GEMM_MAINLOOP()

    int r4 = lane >> 2;
    int c2 = lane & 3;
    fp16* oh = outE + (size_t)bz * strideD;
    float rsum[8];
    #pragma unroll
    for (int r = 0; r < 8; r++) rsum[r] = 0.f;

    #pragma unroll
    for (int mi = 0; mi < 4; mi++) {
        #pragma unroll
        for (int half = 0; half < 2; half++) {
            int m = m0 + wm * 64 + mi * 16 + half * 8 + r4;
            float rs = 0.f;
            #pragma unroll
            for (int ni = 0; ni < 8; ni++) {
                int n = n0 + wn * 64 + ni * 8 + c2 * 2;
                float e0 = __expf(acc[mi][ni][half * 2 + 0] * scale);
                float e1 = __expf(acc[mi][ni][half * 2 + 1] * scale);
                *(uint32_t*)(oh + (size_t)m * ldD + n) = pack2(__float2half(e0), __float2half(e1));
                rs += e0 + e1;
            }
            rsum[mi * 2 + half] = rs;
        }
    }
    #pragma unroll
    for (int r = 0; r < 8; r++) {
        rsum[r] += __shfl_xor_sync(0xffffffffu, rsum[r], 1);
        rsum[r] += __shfl_xor_sync(0xffffffffu, rsum[r], 2);
    }
    __syncthreads();
    float* sp = (float*)smemraw;
    if (c2 == 0) {
        #pragma unroll
        for (int mi = 0; mi < 4; mi++)
            #pragma unroll
            for (int half = 0; half < 2; half++) {
                int rl = wm * 64 + mi * 16 + half * 8 + r4;
                sp[rl * 4 + wn] = rsum[mi * 2 + half];
            }
    }
    __syncthreads();
    if (tid < 128) {
        float s = sp[tid * 4] + sp[tid * 4 + 1] + sp[tid * 4 + 2] + sp[tid * 4 + 3];
        g_part[((size_t)bz * NPX + m0 + tid) * 16 + blockIdx.x] = s;
    }
}

// ---- final GEMM: out = (WpV @ E^T) * inv_rowsum + biasRow + resid, inv computed in-kernel ----
__global__ void gemm_final(
    const fp16* __restrict__ A, int ldA, size_t strideA,
    const fp16* __restrict__ B, int ldB, size_t strideB,
    int K,
    float* __restrict__ outF32, int ldD, size_t strideD,
    const float* __restrict__ biasRow,
    const float* __restrict__ resid)
{
    extern __shared__ char smemraw[];
    int tid = threadIdx.x, wid = tid >> 5, lane = tid & 31;
    int m0 = blockIdx.y * 128, n0 = blockIdx.x * 256, bz = blockIdx.z;
    A += (size_t)bz * strideA;
    B += (size_t)bz * strideB;

    GEMM_MAINLOOP()

    // compute inverse row sums for this CTA's 256 columns from g_part
    float* sp = (float*)smemraw;
    {
        const float* p = g_part + ((size_t)bz * NPX + n0 + tid) * 16;
        float s = 0.f;
        #pragma unroll
        for (int k = 0; k < 16; k++) s += p[k];
        sp[tid] = 1.0f / s;
    }
    __syncthreads();

    int r4 = lane >> 2;
    int c2 = lane & 3;
    float* of = outF32 + (size_t)bz * strideD;
    const float* rp = resid + (size_t)bz * strideD;

    #pragma unroll
    for (int mi = 0; mi < 4; mi++) {
        #pragma unroll
        for (int half = 0; half < 2; half++) {
            int m = m0 + wm * 64 + mi * 16 + half * 8 + r4;
            float brow = biasRow[m];
            #pragma unroll
            for (int ni = 0; ni < 8; ni++) {
                int n = n0 + wn * 64 + ni * 8 + c2 * 2;
                float v0 = acc[mi][ni][half * 2 + 0] * sp[n - n0]     + brow;
                float v1 = acc[mi][ni][half * 2 + 1] * sp[n + 1 - n0] + brow;
                size_t off = (size_t)m * ldD + n;
                float2 q = *(const float2*)(rp + off);
                v0 += q.x; v1 += q.y;
                *(float2*)(of + off) = make_float2(v0, v1);
            }
        }
    }
}

// ---------------- launch ----------------
extern "C" void kernel_launch(void* const* d_in, const int* in_sizes, int n_in,
                              void* d_out, int out_size) {
    const float* x     = (const float*)d_in[0];
    const float* gamma = (const float*)d_in[1];
    const float* beta  = (const float*)d_in[2];
    const float* wq    = (const float*)d_in[3];
    const float* bq    = (const float*)d_in[4];
    const float* wk    = (const float*)d_in[5];
    const float* bk    = (const float*)d_in[6];
    const float* wv    = (const float*)d_in[7];
    const float* bv    = (const float*)d_in[8];
    const float* wp    = (const float*)d_in[9];
    const float* bp    = (const float*)d_in[10];
    float* out = (float*)d_out;

    fp16 *ht, *w, *wvT, *wpv, *qk, *wv16, *E;
    float *bqk, *bpv;
    cudaGetSymbolAddress((void**)&ht, g_ht);
    cudaGetSymbolAddress((void**)&w, g_w);
    cudaGetSymbolAddress((void**)&wvT, g_wvT);
    cudaGetSymbolAddress((void**)&wpv, g_wpv);
    cudaGetSymbolAddress((void**)&qk, g_qk);
    cudaGetSymbolAddress((void**)&wv16, g_wv16);
    cudaGetSymbolAddress((void**)&E, g_E);
    cudaGetSymbolAddress((void**)&bqk, g_bqk);
    cudaGetSymbolAddress((void**)&bpv, g_bpv);

    const int SMEM_DYN = 3 * STG;    // 162 KB
    cudaFuncSetAttribute(gemm_hmma, cudaFuncAttributeMaxDynamicSharedMemorySize, SMEM_DYN);
    cudaFuncSetAttribute(gemm_scores, cudaFuncAttributeMaxDynamicSharedMemorySize, SMEM_DYN);
    cudaFuncSetAttribute(gemm_final, cudaFuncAttributeMaxDynamicSharedMemorySize, SMEM_DYN);

    // fused prep + groupnorm
    prep_all<<<4420, 256>>>(wq, wk, wv, wp, bq, bk, bv);
    gn_kernel<<<64, 256>>>(x, gamma, beta);

    // Wpv = wp @ wv : [512,512] fp16 (small GEMM)
    gemm_hmma<<<dim3(2, 4, 1), 256, SMEM_DYN>>>(
        w + 3 * WS, CCH, 0, wvT, CCH, 0, CCH,
        wpv, CCH, 0, nullptr, nullptr);

    // QK: D[4096,1024] = ht @ [wq;wk]^T + bqk -> fp16
    gemm_hmma<<<dim3(1024 / 256, NPX / 128, 2), 256, SMEM_DYN>>>(
        ht, CCH, NH, w, CCH, 0, CCH,
        qk, 1024, NQK, nullptr, bqk);

    // WpV = Wpv @ ht^T + bpv : [512,4096] fp16
    gemm_hmma<<<dim3(NPX / 256, CCH / 128, 2), 256, SMEM_DYN>>>(
        wpv, CCH, 0, ht, CCH, NH, CCH,
        wv16, NPX, NH, bpv, nullptr);

    // scores -> E = exp(scale * Q@K^T) fp16 + partial sums
    const float scale = 1.0f / sqrtf((float)CCH);
    gemm_scores<<<dim3(NPX / 256, NPX / 128, 2), 256, SMEM_DYN>>>(
        qk, 1024, NQK, qk + 512, 1024, NQK, CCH,
        E, NPX, NN, scale);

    // final: out[c,i] = (sum_j WpV[c,j]*E[i,j]) * invs[i] + bp[c] + x[c,i]
    gemm_final<<<dim3(NPX / 256, CCH / 128, 2), 256, SMEM_DYN>>>(
        wv16, NPX, NH, E, NPX, NN, NPX,
        out, NPX, (size_t)CCH * NPX, bp, x);
}